// round 1
// baseline (speedup 1.0000x reference)
#include <cuda_runtime.h>

// ---------------------------------------------------------------------------
// SpatialGraphConv: out = relu(BN(W @ (x @ adj) + b))  with training-mode BN.
//
// Strategy:
//   k_prep  : zero stat accumulators, transpose W into Wt[c][o] (coalesced use)
//   k_pass<1>: per-tile compute y = W@ (x@adj), accumulate per-channel
//              sum(y_raw), sum(y_raw^2) (bias excluded, folded analytically)
//   k_fold  : derive mean/var per channel, fold BN+bias into A = a*W (stored
//             transposed) and b2 = a*(b-mean)+beta
//   k_pass<2>: recompute y' = A@(x@adj) + b2, relu, store
//
// The inner W-GEMM uses packed fma.rn.f32x2 (2 MACs/inst) since scalar FFMA
// is half-rate (rt_SMSP=2) on sm_103a.
// ---------------------------------------------------------------------------

#define FMA2(d, a, b) asm("fma.rn.f32x2 %0, %1, %2, %0;" : "+l"(d) : "l"(a), "l"(b))

static __device__ float g_sum[128];
static __device__ float g_sumsq[128];
static __device__ float g_Wt[64 * 128];   // Wt[c*128 + o] = W[o*64 + c]
static __device__ float g_At[64 * 128];   // folded, same transposed layout
static __device__ float g_b2[128];

#define BB   64
#define CC   64
#define OO   128
#define TTOT 300
#define VV   25
#define TT_TILE 10
#define COLS    250         // TT_TILE * VV
#define COLS_P  256         // padded (pad cols are zero)
#define NT      30          // TTOT / TT_TILE
#define NBLK    1920        // BB * NT
#define INV_N   (1.0f / 480000.0f)

// shared memory layout (in floats)
#define SM_X    0                         // 64*250 = 16000
#define SM_XG   16000                     // 64*256 = 16384
#define SM_W    (16000 + 16384)           // 8192
#define SM_ADJ  (SM_W + 8192)             // 640 (625 used)
#define SM_B2   (SM_ADJ + 640)            // 128
#define SM_TOTAL (SM_B2 + 128)            // 41344 floats = 165376 bytes

// ---------------------------------------------------------------------------
__global__ void k_prep(const float* __restrict__ W) {
    int tid = threadIdx.x;
    if (tid < 128) { g_sum[tid] = 0.0f; g_sumsq[tid] = 0.0f; }
    for (int i = tid; i < 64 * 128; i += 256) {
        int c = i >> 7, o = i & 127;
        g_Wt[i] = W[o * 64 + c];
    }
}

// ---------------------------------------------------------------------------
__global__ void k_fold(const float* __restrict__ W, const float* __restrict__ b,
                       const float* __restrict__ gamma, const float* __restrict__ beta) {
    int o = threadIdx.x;  // 128 threads
    float s  = g_sum[o] * INV_N;     // E[raw]  (raw = W@xg, no bias)
    float q  = g_sumsq[o] * INV_N;   // E[raw^2]
    float bo = b[o];
    float mean = s + bo;
    float var  = (q + 2.0f * bo * s + bo * bo) - mean * mean;
    float a    = gamma[o] * rsqrtf(var + 1e-5f);
    g_b2[o] = a * (bo - mean) + beta[o];
    for (int c = 0; c < 64; ++c) g_At[c * 128 + o] = a * W[o * 64 + c];
}

// ---------------------------------------------------------------------------
template <int PASS>
__global__ __launch_bounds__(512, 1) void k_pass(const float* __restrict__ x,
                                                 const float* __restrict__ adj,
                                                 float* __restrict__ out) {
    extern __shared__ float sm[];
    float* sX  = sm + SM_X;
    float* sG  = sm + SM_XG;
    float* sW  = sm + SM_W;
    float* sA  = sm + SM_ADJ;
    float* sB2 = sm + SM_B2;

    const int tid = threadIdx.x;
    const int bx  = blockIdx.x;
    const int bb  = bx / NT;
    const int t0  = (bx - bb * NT) * TT_TILE;

    // ---- load X tile (64 channels x 250 contiguous cols each) ----
    const float* gx = x + ((size_t)bb * CC * TTOT + t0) * VV;
    for (int i = tid; i < CC * COLS; i += 512) {
        int c = i / COLS;
        int j = i - c * COLS;
        sX[i] = gx[c * (TTOT * VV) + j];
    }
    const float* wsrc = (PASS == 1) ? g_Wt : g_At;
    for (int i = tid; i < 8192; i += 512) sW[i] = wsrc[i];
    for (int i = tid; i < 625; i += 512) sA[i] = adj[i];
    if (PASS == 2 && tid < 128) sB2[tid] = g_b2[tid];
    __syncthreads();

    // ---- xg = x @ adj : thread owns one output column j, 32 channels ----
    {
        int j  = tid & 255;
        int c0 = (tid >> 8) * 32;
        if (j < COLS) {
            int t = j / 25;
            int w = j - t * 25;
            float aj[25];
#pragma unroll
            for (int v = 0; v < 25; ++v) aj[v] = sA[v * 25 + w];
            const float* xb = sX + t * 25;
#pragma unroll 4
            for (int cc2 = 0; cc2 < 32; ++cc2) {
                const float* xr = xb + (c0 + cc2) * COLS;
                float acc = 0.0f;
#pragma unroll
                for (int v = 0; v < 25; ++v) acc = fmaf(xr[v], aj[v], acc);
                sG[(c0 + cc2) * COLS_P + j] = acc;
            }
        } else {
            for (int cc2 = 0; cc2 < 32; ++cc2) sG[(c0 + cc2) * COLS_P + j] = 0.0f;
        }
    }
    __syncthreads();

    // ---- y = Wt^T @ xg : per-thread 8 o  x 4 column-pairs (f32x2 packed) ----
    const int og = tid >> 5;        // warp id = o-group (broadcast-friendly)
    const int cg = tid & 31;        // lane   = column-pair group
    const int o0 = og * 8;

    unsigned long long acc[8][4];
#pragma unroll
    for (int i = 0; i < 8; ++i)
#pragma unroll
        for (int k = 0; k < 4; ++k) acc[i][k] = 0ull;

#pragma unroll 4
    for (int c = 0; c < 64; ++c) {
        const unsigned long long* xr =
            reinterpret_cast<const unsigned long long*>(sG + c * COLS_P);
        unsigned long long x0 = xr[cg];
        unsigned long long x1 = xr[cg + 32];
        unsigned long long x2 = xr[cg + 64];
        unsigned long long x3 = xr[cg + 96];
        const float* wr = sW + c * 128 + o0;
#pragma unroll
        for (int i = 0; i < 8; ++i) {
            unsigned long long a2;
            asm("mov.b64 %0, {%1, %1};" : "=l"(a2) : "f"(wr[i]));
            FMA2(acc[i][0], a2, x0);
            FMA2(acc[i][1], a2, x1);
            FMA2(acc[i][2], a2, x2);
            FMA2(acc[i][3], a2, x3);
        }
    }

    if (PASS == 1) {
        // per-channel sum / sumsq (pad columns are exact zeros -> contribute 0)
#pragma unroll
        for (int i = 0; i < 8; ++i) {
            float s = 0.0f, q = 0.0f;
#pragma unroll
            for (int k = 0; k < 4; ++k) {
                float lo, hi;
                asm("mov.b64 {%0, %1}, %2;" : "=f"(lo), "=f"(hi) : "l"(acc[i][k]));
                s += lo + hi;
                q = fmaf(lo, lo, q);
                q = fmaf(hi, hi, q);
            }
#pragma unroll
            for (int off = 16; off > 0; off >>= 1) {
                s += __shfl_xor_sync(0xffffffffu, s, off);
                q += __shfl_xor_sync(0xffffffffu, q, off);
            }
            if (cg == 0) {
                atomicAdd(&g_sum[o0 + i], s);
                atomicAdd(&g_sumsq[o0 + i], q);
            }
        }
    } else {
        float* go = out + ((size_t)bb * OO * TTOT + t0) * VV;
#pragma unroll
        for (int i = 0; i < 8; ++i) {
            float b2 = sB2[o0 + i];
            float* gor = go + (o0 + i) * (TTOT * VV);
#pragma unroll
            for (int k = 0; k < 4; ++k) {
                int j = 2 * cg + 64 * k;
                if (j < COLS) {
                    float lo, hi;
                    asm("mov.b64 {%0, %1}, %2;" : "=f"(lo), "=f"(hi) : "l"(acc[i][k]));
                    float2 r;
                    r.x = fmaxf(lo + b2, 0.0f);
                    r.y = fmaxf(hi + b2, 0.0f);
                    *reinterpret_cast<float2*>(gor + j) = r;
                }
            }
        }
    }
}

// ---------------------------------------------------------------------------
extern "C" void kernel_launch(void* const* d_in, const int* in_sizes, int n_in,
                              void* d_out, int out_size) {
    const float* x     = (const float*)d_in[0];
    const float* adj   = (const float*)d_in[1];
    const float* W     = (const float*)d_in[2];
    const float* b     = (const float*)d_in[3];
    const float* gamma = (const float*)d_in[4];
    const float* beta  = (const float*)d_in[5];
    float* out = (float*)d_out;

    const int smem = SM_TOTAL * (int)sizeof(float);
    cudaFuncSetAttribute(k_pass<1>, cudaFuncAttributeMaxDynamicSharedMemorySize, smem);
    cudaFuncSetAttribute(k_pass<2>, cudaFuncAttributeMaxDynamicSharedMemorySize, smem);

    k_prep<<<1, 256>>>(W);
    k_pass<1><<<NBLK, 512, smem>>>(x, adj, nullptr);
    k_fold<<<1, 128>>>(W, b, gamma, beta);
    k_pass<2><<<NBLK, 512, smem>>>(x, adj, out);
}

// round 3
// speedup vs baseline: 1.5528x; 1.5528x over previous
#include <cuda_runtime.h>
#include <cuda_bf16.h>
#include <cstdint>

// ---------------------------------------------------------------------------
// SpatialGraphConv via warp-level HMMA (mma.sync bf16 hi/lo split, f32 accum)
//   k_prep   : zero stats, split W -> bf16 hi/lo SW128 tiles [o][c]
//   k_pass<1>: x tile -> xg = x@adj (fp32) -> split bf16 SW128 [col][c],
//              spill tiles to scratch, HMMA y = W@xg (3 products),
//              stats (sum, sumsq) from accumulators -> atomics
//   k_fold   : fold BN+bias into A = a*W (split hi/lo) and b2
//   k_pass<2>: reload scratch + folded A, HMMA, affine+relu+store
// ---------------------------------------------------------------------------

#define TTOT 300
#define VV   25
#define NT   30
#define NBLK 1920
#define INV_N (1.0f / 480000.0f)

// byte offsets in dynamic smem (tile bases 1024-aligned)
#define XH_OFF    64512    // 256 rows x 128 B = 32768
#define XL_OFF    97280    // 32768
#define AH_OFF    130048   // 128 rows x 128 B = 16384
#define AL_OFF    146432   // 16384
#define ADJ_OFF   162816   // 625 floats
#define SMEM_BYTES 165376

#define SW128(o) ((o) ^ (((o) >> 3) & 0x70))

__device__ __forceinline__ uint32_t smem_u32(const void* p) {
    uint32_t a;
    asm("{ .reg .u64 t; cvta.to.shared.u64 t, %1; cvt.u32.u64 %0, t; }" : "=r"(a) : "l"(p));
    return a;
}

#define LDSM_X4(r0, r1, r2, r3, a) \
    asm volatile("ldmatrix.sync.aligned.m8n8.x4.shared.b16 {%0,%1,%2,%3}, [%4];" \
        : "=r"(r0), "=r"(r1), "=r"(r2), "=r"(r3) : "r"(a))

#define MMA16816(c, a0, a1, a2, a3, b0, b1) \
    asm volatile("mma.sync.aligned.m16n8k16.row.col.f32.bf16.bf16.f32 " \
        "{%0,%1,%2,%3}, {%4,%5,%6,%7}, {%8,%9}, {%0,%1,%2,%3};" \
        : "+f"((c)[0]), "+f"((c)[1]), "+f"((c)[2]), "+f"((c)[3]) \
        : "r"(a0), "r"(a1), "r"(a2), "r"(a3), "r"(b0), "r"(b1))

// ---- globals --------------------------------------------------------------
static __device__ float g_sum[128];
static __device__ float g_sumsq[128];
static __device__ float g_b2[128];
static __device__ __align__(16) unsigned char g_WH[16384];
static __device__ __align__(16) unsigned char g_WL[16384];
static __device__ __align__(16) unsigned char g_AH[16384];
static __device__ __align__(16) unsigned char g_AL[16384];
static __device__ __align__(16) unsigned char g_xg[(size_t)NBLK * 65536];

__device__ __forceinline__ void split_bf16(float v, __nv_bfloat16& h, __nv_bfloat16& l) {
    h = __float2bfloat16(v);
    l = __float2bfloat16(v - __bfloat162float(h));
}

// ---------------------------------------------------------------------------
__global__ void k_prep(const float* __restrict__ W) {
    int tid = threadIdx.x;
    if (tid < 128) { g_sum[tid] = 0.0f; g_sumsq[tid] = 0.0f; }
    for (int i = tid; i < 8192; i += 256) {
        int o = i >> 6, c = i & 63;
        __nv_bfloat16 h, l;
        split_bf16(W[o * 64 + c], h, l);
        unsigned off = SW128((unsigned)(o * 128 + c * 2));
        *(__nv_bfloat16*)(g_WH + off) = h;
        *(__nv_bfloat16*)(g_WL + off) = l;
    }
}

// ---------------------------------------------------------------------------
__global__ void k_fold(const float* __restrict__ W, const float* __restrict__ b,
                       const float* __restrict__ gamma, const float* __restrict__ beta) {
    int o = threadIdx.x;  // 128 threads
    float s  = g_sum[o] * INV_N;
    float q  = g_sumsq[o] * INV_N;
    float bo = b[o];
    float mean = s + bo;
    float var  = (q + 2.0f * bo * s + bo * bo) - mean * mean;
    float a    = gamma[o] * rsqrtf(var + 1e-5f);
    g_b2[o] = a * (bo - mean) + beta[o];
    for (int c = 0; c < 64; ++c) {
        __nv_bfloat16 h, l;
        split_bf16(a * W[o * 64 + c], h, l);
        unsigned off = SW128((unsigned)(o * 128 + c * 2));
        *(__nv_bfloat16*)(g_AH + off) = h;
        *(__nv_bfloat16*)(g_AL + off) = l;
    }
}

// ---------------------------------------------------------------------------
template <int PASS>
__global__ __launch_bounds__(512, 1) void k_pass(const float* __restrict__ x,
                                                 const float* __restrict__ adj,
                                                 float* __restrict__ out) {
    extern __shared__ unsigned char smem[];
    const uint32_t sb = smem_u32(smem);
    const int tid  = threadIdx.x;
    const int wid  = tid >> 5;
    const int lane = tid & 31;
    const int bx   = blockIdx.x;
    const int bb   = bx / NT;
    const int t0   = (bx - bb * NT) * 10;

    if (PASS == 1) {
        float* sX = (float*)smem;
        const float* gx = x + ((size_t)bb * 64 * TTOT + t0) * VV;
        for (int i = tid; i < 16000; i += 512) {
            int c = i / 250, j = i - c * 250;
            sX[i] = gx[c * (TTOT * VV) + j];
        }
        for (int i = tid; i < 1024; i += 512) {
            ((uint4*)(smem + AH_OFF))[i] = ((const uint4*)g_WH)[i];
            ((uint4*)(smem + AL_OFF))[i] = ((const uint4*)g_WL)[i];
        }
        for (int i = tid; i < 625; i += 512) ((float*)(smem + ADJ_OFF))[i] = adj[i];
        if (tid < 128) {  // zero pad rows 248..255 (real 248/249 rewritten below)
            uint4 z = make_uint4(0, 0, 0, 0);
            int tile = tid >> 6, q = tid & 63;
            *(uint4*)(smem + (tile ? XL_OFF : XH_OFF) + 248 * 128 + q * 16) = z;
        }
        __syncthreads();

        // xg = x @ adj, split to bf16 hi/lo, stored transposed [col][c] SW128
        int j  = tid & 255;
        int c0 = (tid >> 8) * 32;
        if (j < 250) {
            int t = j / 25, w = j - t * 25;
            float ajc[25];
#pragma unroll
            for (int v = 0; v < 25; ++v) ajc[v] = ((float*)(smem + ADJ_OFF))[v * 25 + w];
#pragma unroll 4
            for (int cc = 0; cc < 32; ++cc) {
                int c = c0 + cc;
                const float* xr = sX + c * 250 + t * 25;
                float acc = 0.0f;
#pragma unroll
                for (int v = 0; v < 25; ++v) acc = fmaf(xr[v], ajc[v], acc);
                __nv_bfloat16 h, l;
                split_bf16(acc, h, l);
                unsigned off = SW128((unsigned)(j * 128 + c * 2));
                *(__nv_bfloat16*)(smem + XH_OFF + off) = h;
                *(__nv_bfloat16*)(smem + XL_OFF + off) = l;
            }
        }
        __syncthreads();

        // spill raw split tiles (overlaps with subsequent MMA issue)
        uint4* dst = (uint4*)(g_xg + (size_t)bx * 65536);
        const uint4* sH = (const uint4*)(smem + XH_OFF);
        const uint4* sL = (const uint4*)(smem + XL_OFF);
        for (int i = tid; i < 2048; i += 512) { dst[i] = sH[i]; dst[2048 + i] = sL[i]; }
    } else {
        const uint4* src = (const uint4*)(g_xg + (size_t)bx * 65536);
        uint4* dH = (uint4*)(smem + XH_OFF);
        uint4* dL = (uint4*)(smem + XL_OFF);
        for (int i = tid; i < 2048; i += 512) { dH[i] = src[i]; dL[i] = src[2048 + i]; }
        for (int i = tid; i < 1024; i += 512) {
            ((uint4*)(smem + AH_OFF))[i] = ((const uint4*)g_AH)[i];
            ((uint4*)(smem + AL_OFF))[i] = ((const uint4*)g_AL)[i];
        }
        __syncthreads();
    }

    // ---- HMMA: y[128 x 256] = W @ xg, 3-product bf16 split ---------------
    // warp tile: m32 x n64.  warp_m = wid&3 (4 x 32 = 128 o-rows),
    //                        warp_n = wid>>2 (4 x 64 = 256 cols)
    const int r   = lane & 7;
    const int mid = lane >> 3;
    const int m0  = (wid & 3) * 32;
    const int n0  = (wid >> 2) * 64;
    const int swx = r << 4;   // SW128 XOR term (row&7 == r for all tile rows)

    uint32_t a_rowoff[2], b_rowoff[4];
#pragma unroll
    for (int mt = 0; mt < 2; ++mt)
        a_rowoff[mt] = (uint32_t)(m0 + mt * 16 + ((mid & 1) << 3) + r) * 128u;
#pragma unroll
    for (int np = 0; np < 4; ++np)
        b_rowoff[np] = (uint32_t)(n0 + np * 16 + ((mid & 2) << 2) + r) * 128u;

    float acc[2][8][4];
#pragma unroll
    for (int mt = 0; mt < 2; ++mt)
#pragma unroll
        for (int nt = 0; nt < 8; ++nt)
#pragma unroll
            for (int e = 0; e < 4; ++e) acc[mt][nt][e] = 0.0f;

    const uint32_t Aoff[3] = {AH_OFF, AH_OFF, AL_OFF};
    const uint32_t Boff[3] = {XH_OFF, XL_OFF, XH_OFF};

#pragma unroll
    for (int p = 0; p < 3; ++p) {
        const uint32_t Abase = sb + Aoff[p];
        const uint32_t Bbase = sb + Boff[p];
#pragma unroll
        for (int ks = 0; ks < 4; ++ks) {
            const uint32_t ca = (uint32_t)(ks * 32 + ((mid & 2) << 3)) ^ swx;
            const uint32_t cb = (uint32_t)(ks * 32 + ((mid & 1) << 4)) ^ swx;
            uint32_t a[2][4];
#pragma unroll
            for (int mt = 0; mt < 2; ++mt)
                LDSM_X4(a[mt][0], a[mt][1], a[mt][2], a[mt][3],
                        Abase + a_rowoff[mt] + ca);
#pragma unroll
            for (int np = 0; np < 4; ++np) {
                uint32_t b0, b1, b2, b3;
                LDSM_X4(b0, b1, b2, b3, Bbase + b_rowoff[np] + cb);
                MMA16816(acc[0][2 * np],     a[0][0], a[0][1], a[0][2], a[0][3], b0, b1);
                MMA16816(acc[0][2 * np + 1], a[0][0], a[0][1], a[0][2], a[0][3], b2, b3);
                MMA16816(acc[1][2 * np],     a[1][0], a[1][1], a[1][2], a[1][3], b0, b1);
                MMA16816(acc[1][2 * np + 1], a[1][0], a[1][1], a[1][2], a[1][3], b2, b3);
            }
        }
    }

    if (PASS == 1) {
        // stats: rows r0 = m0 + mt*16 + lane/4, r1 = r0 + 8 (pad cols are 0)
#pragma unroll
        for (int mt = 0; mt < 2; ++mt) {
            float s0 = 0.0f, q0 = 0.0f, s1 = 0.0f, q1 = 0.0f;
#pragma unroll
            for (int nt = 0; nt < 8; ++nt) {
                float c0 = acc[mt][nt][0], c1 = acc[mt][nt][1];
                float c2 = acc[mt][nt][2], c3 = acc[mt][nt][3];
                s0 += c0 + c1; q0 = fmaf(c0, c0, fmaf(c1, c1, q0));
                s1 += c2 + c3; q1 = fmaf(c2, c2, fmaf(c3, c3, q1));
            }
#pragma unroll
            for (int off = 1; off <= 2; off <<= 1) {
                s0 += __shfl_xor_sync(0xffffffffu, s0, off);
                q0 += __shfl_xor_sync(0xffffffffu, q0, off);
                s1 += __shfl_xor_sync(0xffffffffu, s1, off);
                q1 += __shfl_xor_sync(0xffffffffu, q1, off);
            }
            if ((lane & 3) == 0) {
                int row0 = m0 + mt * 16 + (lane >> 2);
                atomicAdd(&g_sum[row0], s0);
                atomicAdd(&g_sumsq[row0], q0);
                atomicAdd(&g_sum[row0 + 8], s1);
                atomicAdd(&g_sumsq[row0 + 8], q1);
            }
        }
    } else {
#pragma unroll
        for (int mt = 0; mt < 2; ++mt) {
            int row0 = m0 + mt * 16 + (lane >> 2);
            float bza = g_b2[row0];
            float bzb = g_b2[row0 + 8];
            float* base0 = out + ((size_t)(bb * 128 + row0)) * (TTOT * VV) + t0 * VV;
            float* base1 = base0 + 8 * (TTOT * VV);
#pragma unroll
            for (int nt = 0; nt < 8; ++nt) {
                int j = n0 + nt * 8 + (lane & 3) * 2;
                if (j < 250) {
                    float2 v0, v1;
                    v0.x = fmaxf(acc[mt][nt][0] + bza, 0.0f);
                    v0.y = fmaxf(acc[mt][nt][1] + bza, 0.0f);
                    v1.x = fmaxf(acc[mt][nt][2] + bzb, 0.0f);
                    v1.y = fmaxf(acc[mt][nt][3] + bzb, 0.0f);
                    *(float2*)(base0 + j) = v0;
                    *(float2*)(base1 + j) = v1;
                }
            }
        }
    }
}

// ---------------------------------------------------------------------------
extern "C" void kernel_launch(void* const* d_in, const int* in_sizes, int n_in,
                              void* d_out, int out_size) {
    const float* x     = (const float*)d_in[0];
    const float* adj   = (const float*)d_in[1];
    const float* W     = (const float*)d_in[2];
    const float* b     = (const float*)d_in[3];
    const float* gamma = (const float*)d_in[4];
    const float* beta  = (const float*)d_in[5];
    float* out = (float*)d_out;

    cudaFuncSetAttribute(k_pass<1>, cudaFuncAttributeMaxDynamicSharedMemorySize, SMEM_BYTES);
    cudaFuncSetAttribute(k_pass<2>, cudaFuncAttributeMaxDynamicSharedMemorySize, SMEM_BYTES);

    k_prep<<<1, 256>>>(W);
    k_pass<1><<<NBLK, 512, SMEM_BYTES>>>(x, adj, nullptr);
    k_fold<<<1, 128>>>(W, b, gamma, beta);
    k_pass<2><<<NBLK, 512, SMEM_BYTES>>>(x, adj, out);
}